// round 1
// baseline (speedup 1.0000x reference)
#include <cuda_runtime.h>
#include <cstdint>

// TreeAttention: N=8, T_DST=512, T_SRC=4096, HID=64, K=64, W0=64,
// SCALE_UP=2, OVERSAMPLE=1.5. One CTA (128 threads) per (n, a) row.
//
// Iteration schedule (static):
//   it: 0..6, w = 64,128,256,512,1024,2048,4096
//   Z  = 96 (it0) else 128
//   tks_max = 63 (it0), 64 (it6), else 96
//   max_z   = 64 (it6) else 128
//   mult    = 1.0 (it6) else 1.5
// pmask is always a prefix mask (idx < V).

#define NEGV  (-32000.0f)
#define FMINV (-1e30f)

__global__ __launch_bounds__(128, 8)
void tree_attn_kernel(const float* __restrict__ q,
                      const float* __restrict__ k,
                      const float* __restrict__ v,
                      float* __restrict__ out)
{
    const int row = blockIdx.x;          // n*512 + a
    const int n   = row >> 9;
    const int a   = row & 511;
    const int t   = threadIdx.x;         // 0..127

    __shared__ float    qs[64];
    __shared__ int      pix[128];
    __shared__ float    sc[128];
    __shared__ int      np[128];
    __shared__ unsigned bm[128];         // 4096-bit value bitmap
    __shared__ int      cnt[128];
    __shared__ float    pr[64];

    const float  tsrc = (float)(3585 + a);     // T_SRC - T_DST + 1 + a
    const float* kb   = k + (size_t)n * 4096 * 64;
    const float* vb   = v + (size_t)n * 4096 * 64;

    if (t < 64) qs[t] = q[(size_t)row * 64 + t];
    pix[t] = (t < 96) ? t : 0;
    __syncthreads();

    float ws = 64.0f;
    int   V  = 64;     // valid (pmask) prefix count
    int   Z  = 96;     // current pixel buffer width

    #pragma unroll 1
    for (int it = 0; it < 7; ++it) {
        const bool  last    = (it == 6);
        const float mult    = last ? 1.0f : 1.5f;
        const int   tks_max = (it == 0) ? 63 : (last ? 64 : 96);
        const int   max_z   = last ? 64 : 128;

        // ---- scores: s[z] = q . k[min(round(pix*tsrc/ws),4095)] or NEG ----
        if (t < Z) {
            float s = NEGV;
            if (t < V) {
                const float ratio = __fdiv_rn(tsrc, ws);
                int x = (int)rintf(__fmul_rn((float)pix[t], ratio));
                x = min(x, 4095);
                const float4* kr = (const float4*)(kb + (size_t)x * 64);
                const float4* qr = (const float4*)qs;
                float acc = 0.0f;
                #pragma unroll
                for (int i = 0; i < 16; ++i) {
                    float4 kk4 = __ldg(&kr[i]);
                    float4 qq4 = qr[i];
                    acc += kk4.x*qq4.x + kk4.y*qq4.y + kk4.z*qq4.z + kk4.w*qq4.w;
                }
                s = acc;
            }
            sc[t] = s;
        }
        __syncthreads();

        // ---- tks = clip(round(ws/tsrc * 64 * mult), 1, min(ws-1, Z-1)) ----
        float tkf = rintf(__fmul_rn(__fmul_rn(__fdiv_rn(ws, tsrc), 64.0f), mult));
        tkf = fminf(fmaxf(tkf, 1.0f), fminf(ws - 1.0f, (float)(Z - 1)));
        const int tks = (int)tkf;
        const int tks_eff = min(tks, tks_max);   // effective valid prefix after topk

        // ---- stable descending top-k via rank (ties -> lower index first) ----
        if (t < Z) {
            const float sv = sc[t];
            int rank = 0;
            for (int j = 0; j < Z; ++j) {
                const float o = sc[j];
                rank += (int)((o > sv) || (o == sv && j < t));
            }
            if (rank < tks_max) np[rank] = pix[t];
            if (t >= tks_max)   np[t]   = 0;     // jnp.pad with zeros
        }
        bm[t] = 0u;
        __syncthreads();

        // ---- scale-up children into bitmap ----
        const float wsn   = fminf(tsrc, __fmul_rn(ws, 2.0f));
        const float scale = __fdiv_rn(wsn, ws);
        if (t < Z) {
            const int p  = np[t];
            int p0 = (int)rintf(__fmul_rn((float)p, scale));
            p0 = min(max(p0, 0), 4095);
            atomicOr(&bm[p0 >> 5], 1u << (p0 & 31));
            if (t < tks_eff) {
                const int p1 = (int)rintf(__fmul_rn((float)(p + 1), scale));
                if (p1 - p0 >= 2) {
                    const int pv = min(p0 + 1, 4095);
                    atomicOr(&bm[pv >> 5], 1u << (pv & 31));
                }
            }
        }
        __syncthreads();

        // ---- sorted-unique extraction from bitmap (ascending), truncate ----
        cnt[t] = __popc(bm[t]);
        __syncthreads();
        int off = 0, total = 0;
        #pragma unroll 8
        for (int u = 0; u < 128; ++u) {
            const int c = cnt[u];
            total += c;
            off   += (u < t) ? c : 0;
        }
        unsigned m = bm[t];
        while (m != 0u && off < max_z) {
            const int b = __ffs(m) - 1;
            pix[off] = (t << 5) + b;
            m &= (m - 1u);
            ++off;
        }
        const int Vn = min(total, max_z);
        if (t >= Vn) pix[t] = 0;                 // where(ps<0, 0, ps)
        __syncthreads();

        V  = Vn;
        Z  = 128;
        ws = wsn;
    }

    // ---- final sparse attention over 64 slots ----
    float e = 0.0f;
    if (t < 64) {
        float s = FMINV;
        if (t < V) {
            const int x = min(pix[t], 4095);
            const float4* kr = (const float4*)(kb + (size_t)x * 64);
            const float4* qr = (const float4*)qs;
            float acc = 0.0f;
            #pragma unroll
            for (int i = 0; i < 16; ++i) {
                float4 kk4 = __ldg(&kr[i]);
                float4 qq4 = qr[i];
                acc += kk4.x*qq4.x + kk4.y*qq4.y + kk4.z*qq4.z + kk4.w*qq4.w;
            }
            s = acc;
        }
        sc[t] = s;
    }
    __syncthreads();

    if (t < 64) {
        float mx = sc[0];
        #pragma unroll 8
        for (int j = 1; j < 64; ++j) mx = fmaxf(mx, sc[j]);
        e = expf(sc[t] - mx);
        pr[t] = e;
    }
    __syncthreads();
    if (t < 64) {
        float sum = 0.0f;
        #pragma unroll 8
        for (int j = 0; j < 64; ++j) sum += pr[j];
        __syncthreads();        // all reads of pr done before overwrite
        pr[t] = e / sum;
    } else {
        __syncthreads();
    }
    __syncthreads();

    if (t < 64) {
        float acc = 0.0f;
        #pragma unroll 4
        for (int z = 0; z < 64; ++z) {
            const int x = min(pix[z], 4095);
            acc += pr[z] * __ldg(&vb[(size_t)x * 64 + t]);
        }
        out[(size_t)row * 64 + t] = acc;
    }
}

extern "C" void kernel_launch(void* const* d_in, const int* in_sizes, int n_in,
                              void* d_out, int out_size)
{
    const float* q = (const float*)d_in[0];   // (8, 512, 64)
    const float* k = (const float*)d_in[1];   // (8, 4096, 64)
    const float* v = (const float*)d_in[2];   // (8, 4096, 64)
    float* out = (float*)d_out;               // (8, 512, 64)
    (void)in_sizes; (void)n_in; (void)out_size;

    tree_attn_kernel<<<8 * 512, 128>>>(q, k, v, out);
}

// round 2
// speedup vs baseline: 2.2367x; 2.2367x over previous
#include <cuda_runtime.h>
#include <cstdint>

// TreeAttention: N=8, T_DST=512, T_SRC=4096, HID=64, K=64, W0=64,
// SCALE_UP=2, OVERSAMPLE=1.5. One CTA (128 threads) per (n, a) row.
// Static schedule: it=0..6, w=64..4096; Z=96(it0)/128; tks_max=63/96/64(last);
// max_z=128 (64 last); mult=1.5 (1.0 last). pmask is always a prefix mask.

#define NEGV  (-32000.0f)
#define FMINV (-1e30f)

__global__ __launch_bounds__(128, 8)
void tree_attn_kernel(const float* __restrict__ q,
                      const float* __restrict__ k,
                      const float* __restrict__ v,
                      float* __restrict__ out)
{
    const int row  = blockIdx.x;          // n*512 + a
    const int n    = row >> 9;
    const int a    = row & 511;
    const int t    = threadIdx.x;         // 0..127
    const int lane = t & 31;
    const int wid  = t >> 5;
    const int qc   = t & 3;               // quad channel (16B chunk)
    const int qr   = t >> 2;              // quad row (0..31)

    __shared__ __align__(16) float qs[64];
    __shared__ __align__(16) float sc[128];
    __shared__ __align__(16) float pr[64];
    __shared__ int      pix[128];
    __shared__ int      np[128];
    __shared__ unsigned bm[128];          // 4096-bit value bitmap
    __shared__ int      wsum[4];

    const float  tsrc = (float)(3585 + a);        // T_SRC - T_DST + 1 + a
    const float* kb   = k + (size_t)n * (4096 * 64);
    const float* vb   = v + (size_t)n * (4096 * 64);

    if (t < 64) qs[t] = q[(size_t)row * 64 + t];
    pix[t] = (t < 96) ? t : 0;
    __syncthreads();

    float ws = 64.0f;
    int   V  = 64;                        // valid (pmask) prefix length

    #pragma unroll 1
    for (int it = 0; it < 7; ++it) {
        const bool  last    = (it == 6);
        const float mult    = last ? 1.0f : 1.5f;
        const int   tks_max = (it == 0) ? 63 : (last ? 64 : 96);
        const int   max_z   = last ? 64 : 128;
        const int   Zcur    = (it == 0) ? 96 : 128;

        // ---- phase A: scores via quad-cooperative gather; clear np/bm ----
        const float ratio = __fdiv_rn(tsrc, ws);
        #pragma unroll 1
        for (int pass = 0; pass < 4; ++pass) {
            const int  r     = pass * 32 + qr;
            const bool valid = (r < V);
            float acc = 0.0f;
            if (valid) {
                const int x = min((int)rintf(__fmul_rn((float)pix[r], ratio)), 4095);
                const float4* kr = (const float4*)(kb + (size_t)x * 64) + qc;
                const float4* qp = (const float4*)qs + qc;
                #pragma unroll
                for (int i = 0; i < 4; ++i) {
                    float4 kk = __ldg(kr + i * 4);
                    float4 qq = qp[i * 4];
                    acc += kk.x*qq.x + kk.y*qq.y + kk.z*qq.z + kk.w*qq.w;
                }
            }
            acc += __shfl_xor_sync(0xFFFFFFFFu, acc, 1);
            acc += __shfl_xor_sync(0xFFFFFFFFu, acc, 2);
            if (qc == 0) sc[r] = valid ? acc : NEGV;
        }
        np[t] = 0;           // analytic rank for NEG entries -> pixel 0 (pad)
        bm[t] = 0u;
        __syncthreads();

        // ---- stable descending rank over the V valid scores only ----
        if (t < V) {
            const float  sv  = sc[t];
            const int    nj4 = (V + 3) >> 2;
            const float4* s4 = (const float4*)sc;
            int rank = 0;
            for (int j4 = 0; j4 < nj4; ++j4) {
                const float4 o  = s4[j4];
                const int    jb = j4 << 2;
                rank += (int)((o.x > sv) || (o.x == sv && (jb + 0) < t));
                rank += (int)((o.y > sv) || (o.y == sv && (jb + 1) < t));
                rank += (int)((o.z > sv) || (o.z == sv && (jb + 2) < t));
                rank += (int)((o.w > sv) || (o.w == sv && (jb + 3) < t));
            }
            if (rank < tks_max) np[rank] = pix[t];
        }
        __syncthreads();

        // ---- tks = clip(round(ws/tsrc*64*mult), 1, min(ws-1, Z-1)) ----
        float tkf = rintf(__fmul_rn(__fmul_rn(__fdiv_rn(ws, tsrc), 64.0f), mult));
        tkf = fminf(fmaxf(tkf, 1.0f), fminf(ws - 1.0f, (float)(Zcur - 1)));
        const int tks_eff = min((int)tkf, tks_max);

        // ---- scale-up children into bitmap ----
        const float wsn   = fminf(tsrc, __fmul_rn(ws, 2.0f));
        const float scale = __fdiv_rn(wsn, ws);
        if (t < tks_max) {
            const int p  = np[t];
            const int p0 = min((int)rintf(__fmul_rn((float)p, scale)), 4095);
            atomicOr(&bm[p0 >> 5], 1u << (p0 & 31));
            if (t < tks_eff) {
                const int p1 = (int)rintf(__fmul_rn((float)(p + 1), scale));
                if (p1 - p0 >= 2) {
                    const int pv = min(p0 + 1, 4095);
                    atomicOr(&bm[pv >> 5], 1u << (pv & 31));
                }
            }
        }
        if (t == 127) atomicOr(&bm[0], 1u);   // pad zeros (tks_max < Z always)
        __syncthreads();

        // ---- parallel scan + sorted-unique extraction ----
        unsigned mw = bm[t];
        const int c = __popc(mw);
        int inc = c;
        #pragma unroll
        for (int d = 1; d < 32; d <<= 1) {
            const int o = __shfl_up_sync(0xFFFFFFFFu, inc, d);
            if (lane >= d) inc += o;
        }
        if (lane == 31) wsum[wid] = inc;
        __syncthreads();
        int base = 0, total = 0;
        #pragma unroll
        for (int w2 = 0; w2 < 4; ++w2) {
            const int s = wsum[w2];
            if (w2 < wid) base += s;
            total += s;
        }
        int off = base + inc - c;             // exclusive prefix
        while (mw != 0u && off < max_z) {
            const int b = __ffs(mw) - 1;
            pix[off] = (t << 5) + b;
            mw &= (mw - 1u);
            ++off;
        }
        const int Vn = min(total, max_z);
        if (t >= Vn) pix[t] = 0;              // where(ps<0, 0, ps)
        __syncthreads();

        V  = Vn;
        ws = wsn;
    }

    // ---- final scores over 64 slots (quad-cooperative) ----
    {
        const float4* qp = (const float4*)qs + qc;
        #pragma unroll 1
        for (int pass = 0; pass < 2; ++pass) {
            const int  r     = pass * 32 + qr;
            const bool valid = (r < V);
            float acc = 0.0f;
            if (valid) {
                const int x = min(pix[r], 4095);
                const float4* kr = (const float4*)(kb + (size_t)x * 64) + qc;
                #pragma unroll
                for (int i = 0; i < 4; ++i) {
                    float4 kk = __ldg(kr + i * 4);
                    float4 qq = qp[i * 4];
                    acc += kk.x*qq.x + kk.y*qq.y + kk.z*qq.z + kk.w*qq.w;
                }
            }
            acc += __shfl_xor_sync(0xFFFFFFFFu, acc, 1);
            acc += __shfl_xor_sync(0xFFFFFFFFu, acc, 2);
            if (qc == 0) sc[r] = valid ? acc : FMINV;
        }
    }
    __syncthreads();

    // ---- softmax numerators ----
    if (t < 64) {
        float mx = FMINV;
        const float4* s4 = (const float4*)sc;
        #pragma unroll
        for (int i = 0; i < 16; ++i) {
            const float4 vv = s4[i];
            mx = fmaxf(mx, fmaxf(fmaxf(vv.x, vv.y), fmaxf(vv.z, vv.w)));
        }
        pr[t] = expf(sc[t] - mx);
    }
    __syncthreads();

    float denom = 0.0f;
    {
        const float4* p4 = (const float4*)pr;
        #pragma unroll
        for (int i = 0; i < 16; ++i) {
            const float4 vv = p4[i];
            denom += vv.x + vv.y + vv.z + vv.w;
        }
    }

    // ---- weighted V gather: 128 threads = 64 cols x 2 z-halves ----
    const int col = t & 63;
    const int zh  = t >> 6;
    float acc = 0.0f;
    #pragma unroll 4
    for (int z = zh * 32; z < zh * 32 + 32; ++z) {
        acc += pr[z] * __ldg(&vb[(size_t)pix[z] * 64 + col]);
    }
    __syncthreads();
    sc[t] = acc;
    __syncthreads();
    if (t < 64)
        out[(size_t)row * 64 + t] = (sc[t] + sc[t + 64]) / denom;
}

extern "C" void kernel_launch(void* const* d_in, const int* in_sizes, int n_in,
                              void* d_out, int out_size)
{
    const float* q = (const float*)d_in[0];   // (8, 512, 64)
    const float* k = (const float*)d_in[1];   // (8, 4096, 64)
    const float* v = (const float*)d_in[2];   // (8, 4096, 64)
    float* out = (float*)d_out;               // (8, 512, 64)
    (void)in_sizes; (void)n_in; (void)out_size;

    tree_attn_kernel<<<8 * 512, 128>>>(q, k, v, out);
}

// round 4
// speedup vs baseline: 2.4255x; 1.0844x over previous
#include <cuda_runtime.h>
#include <cstdint>

// TreeAttention: N=8, T_DST=512, T_SRC=4096, HID=64, K=64, W0=64,
// SCALE_UP=2, OVERSAMPLE=1.5. One CTA (128 threads) per (n, a) row.
// Static schedule: it=0..6; Z=96(it0)/128; tks_max=63/96/64(last);
// max_z=128 (64 last); mult=1.5 (1.0 last). pmask is always a prefix mask.
//
// Exactness notes:
//  - ratio = tsrc/ws >= 1 always => distinct pixels map to distinct k rows
//    => valid scores are pairwise distinct (no fp-exact ties in practice);
//    NEGV-tail ties rank stably to their own index, handled by np[] default.
//  - round-half-even via rintf; __fdiv_rn/__fmul_rn avoid fast-math rewrites.
//  - All warp collectives run with block-uniform trip counts (V is shared
//    state) — per-lane work is predicated, never the loop bound.

#define NEGV  (-32000.0f)
#define FMINV (-1e30f)

__global__ __launch_bounds__(128, 8)
void tree_attn_kernel(const float* __restrict__ q,
                      const float* __restrict__ k,
                      const float* __restrict__ v,
                      float* __restrict__ out)
{
    const int row  = blockIdx.x;          // n*512 + a
    const int n    = row >> 9;
    const int a    = row & 511;
    const int t    = threadIdx.x;         // 0..127
    const int lane = t & 31;
    const int wid  = t >> 5;
    const int qc   = t & 3;               // quad channel (16B chunk)
    const int qr   = t >> 2;              // quad row (0..31)

    __shared__ __align__(16) float qs[64];
    __shared__ __align__(16) float sc[128];
    __shared__ __align__(16) float pr[64];
    __shared__ int      pix[128];
    __shared__ int      np[128];
    __shared__ unsigned bm[128];          // 4096-bit value bitmap
    __shared__ int      wsum[4];

    const float  tsrc = (float)(3585 + a);        // T_SRC - T_DST + 1 + a
    const float* kb   = k + (size_t)n * (4096 * 64);
    const float* vb   = v + (size_t)n * (4096 * 64);

    if (t < 64) qs[t] = q[(size_t)row * 64 + t];
    pix[t] = (t < 96) ? t : 0;
    __syncthreads();

    float ws = 64.0f;
    int   V  = 64;                        // valid (pmask) prefix length

    #pragma unroll 1
    for (int it = 0; it < 7; ++it) {
        const bool  last    = (it == 6);
        const float mult    = last ? 1.0f : 1.5f;
        const int   tks_max = (it == 0) ? 63 : (last ? 64 : 96);
        const int   max_z   = last ? 64 : 128;
        const int   Zcur    = (it == 0) ? 96 : 128;

        // ---- phase A: scores via quad-cooperative gather ----
        // npass is block-uniform (V is shared state) -> uniform trip count;
        // per-lane validity only predicates the memory work, not the shfls.
        const float ratio = __fdiv_rn(tsrc, ws);
        if (t >= V) sc[t] = NEGV;         // tail: masked scores
        {
            const int npass = (V + 31) >> 5;
            const float4* qp = (const float4*)qs + qc;
            #pragma unroll 1
            for (int pass = 0; pass < npass; ++pass) {
                const int  r     = pass * 32 + qr;
                const bool valid = (r < V);
                float acc = 0.0f;
                if (valid) {
                    const int x = min((int)rintf(__fmul_rn((float)pix[r], ratio)), 4095);
                    const float4* kr = (const float4*)(kb + (size_t)x * 64) + qc;
                    #pragma unroll
                    for (int i = 0; i < 4; ++i) {
                        float4 kk = __ldg(kr + i * 4);
                        float4 qq = qp[i * 4];
                        acc += kk.x*qq.x + kk.y*qq.y + kk.z*qq.z + kk.w*qq.w;
                    }
                }
                acc += __shfl_xor_sync(0xFFFFFFFFu, acc, 1);
                acc += __shfl_xor_sync(0xFFFFFFFFu, acc, 2);
                if (valid && qc == 0) sc[r] = acc;
            }
        }
        np[t] = 0;           // rank t for NEG tail -> pixel 0 (pad); overwritten below
        bm[t] = 0u;
        __syncthreads();

        // ---- descending rank over V valid, pairwise-distinct scores ----
        if (t < V) {
            const float  sv  = sc[t];
            const int    nj4 = (V + 3) >> 2;  // sc tail is NEGV (< sv), safe
            const float4* s4 = (const float4*)sc;
            int rank = 0;
            #pragma unroll 4
            for (int j4 = 0; j4 < nj4; ++j4) {
                const float4 o = s4[j4];
                rank += (int)(o.x > sv);
                rank += (int)(o.y > sv);
                rank += (int)(o.z > sv);
                rank += (int)(o.w > sv);
            }
            if (rank < tks_max) np[rank] = pix[t];
        }
        __syncthreads();

        // ---- tks = clip(round(ws/tsrc*64*mult), 1, min(ws-1, Z-1)) ----
        float tkf = rintf(__fmul_rn(__fmul_rn(__fdiv_rn(ws, tsrc), 64.0f), mult));
        tkf = fminf(fmaxf(tkf, 1.0f), fminf(ws - 1.0f, (float)(Zcur - 1)));
        const int tks_eff = min((int)tkf, tks_max);

        // ---- scale-up children into bitmap ----
        const float wsn   = fminf(tsrc, __fmul_rn(ws, 2.0f));
        const float scale = __fdiv_rn(wsn, ws);
        if (t < tks_max) {
            const int p  = np[t];
            const int p0 = min((int)rintf(__fmul_rn((float)p, scale)), 4095);
            atomicOr(&bm[p0 >> 5], 1u << (p0 & 31));
            if (t < tks_eff) {
                const int p1 = (int)rintf(__fmul_rn((float)(p + 1), scale));
                if (p1 - p0 >= 2) {
                    const int pv = min(p0 + 1, 4095);
                    atomicOr(&bm[pv >> 5], 1u << (pv & 31));
                }
            }
        }
        if (t == 127) atomicOr(&bm[0], 1u);   // pad zeros (tks_max < Z always)
        __syncthreads();

        // ---- parallel scan + sorted-unique extraction ----
        unsigned mw = bm[t];
        const int c = __popc(mw);
        int inc = c;
        #pragma unroll
        for (int d = 1; d < 32; d <<= 1) {
            const int o = __shfl_up_sync(0xFFFFFFFFu, inc, d);
            if (lane >= d) inc += o;
        }
        if (lane == 31) wsum[wid] = inc;
        __syncthreads();
        int base = 0, total = 0;
        #pragma unroll
        for (int w2 = 0; w2 < 4; ++w2) {
            const int s = wsum[w2];
            if (w2 < wid) base += s;
            total += s;
        }
        int off = base + inc - c;             // exclusive prefix
        while (mw != 0u && off < max_z) {
            const int b = __ffs(mw) - 1;
            pix[off] = (t << 5) + b;
            mw &= (mw - 1u);
            ++off;
        }
        const int Vn = min(total, max_z);
        if (t >= Vn) pix[t] = 0;              // where(ps<0, 0, ps)
        __syncthreads();

        V  = Vn;
        ws = wsn;
    }

    // ---- final scores over 64 slots (quad-cooperative, uniform trips) ----
    {
        if (t >= V && t < 64) sc[t] = FMINV;
        const int npass = (V + 31) >> 5;
        const float4* qp = (const float4*)qs + qc;
        #pragma unroll 1
        for (int pass = 0; pass < npass; ++pass) {
            const int  r     = pass * 32 + qr;
            const bool valid = (r < V);
            float acc = 0.0f;
            if (valid) {
                const int x = min(pix[r], 4095);
                const float4* kr = (const float4*)(kb + (size_t)x * 64) + qc;
                #pragma unroll
                for (int i = 0; i < 4; ++i) {
                    float4 kk = __ldg(kr + i * 4);
                    float4 qq = qp[i * 4];
                    acc += kk.x*qq.x + kk.y*qq.y + kk.z*qq.z + kk.w*qq.w;
                }
            }
            acc += __shfl_xor_sync(0xFFFFFFFFu, acc, 1);
            acc += __shfl_xor_sync(0xFFFFFFFFu, acc, 2);
            if (valid && qc == 0) sc[r] = acc;
        }
    }
    __syncthreads();

    // ---- softmax numerators ----
    if (t < 64) {
        float mx = FMINV;
        const float4* s4 = (const float4*)sc;
        #pragma unroll
        for (int i = 0; i < 16; ++i) {
            const float4 vv = s4[i];
            mx = fmaxf(mx, fmaxf(fmaxf(vv.x, vv.y), fmaxf(vv.z, vv.w)));
        }
        pr[t] = __expf(sc[t] - mx);
    }
    __syncthreads();

    float denom = 0.0f;
    {
        const float4* p4 = (const float4*)pr;
        #pragma unroll
        for (int i = 0; i < 16; ++i) {
            const float4 vv = p4[i];
            denom += vv.x + vv.y + vv.z + vv.w;
        }
    }

    // ---- weighted V gather: 128 threads = 64 cols x 2 z-halves ----
    const int col = t & 63;
    const int zh  = t >> 6;
    float acc = 0.0f;
    #pragma unroll 4
    for (int z = zh * 32; z < zh * 32 + 32; ++z) {
        acc += pr[z] * __ldg(&vb[(size_t)pix[z] * 64 + col]);
    }
    __syncthreads();
    sc[t] = acc;
    __syncthreads();
    if (t < 64)
        out[(size_t)row * 64 + t] = (sc[t] + sc[t + 64]) / denom;
}

extern "C" void kernel_launch(void* const* d_in, const int* in_sizes, int n_in,
                              void* d_out, int out_size)
{
    const float* q = (const float*)d_in[0];   // (8, 512, 64)
    const float* k = (const float*)d_in[1];   // (8, 4096, 64)
    const float* v = (const float*)d_in[2];   // (8, 4096, 64)
    float* out = (float*)d_out;               // (8, 512, 64)
    (void)in_sizes; (void)n_in; (void)out_size;

    tree_attn_kernel<<<8 * 512, 128>>>(q, k, v, out);
}

// round 5
// speedup vs baseline: 2.5922x; 1.0687x over previous
#include <cuda_runtime.h>
#include <cstdint>

// TreeAttention: N=8, T_DST=512, T_SRC=4096, HID=64, K=64, W0=64,
// SCALE_UP=2, OVERSAMPLE=1.5. One CTA (128 threads) per (n, a) row.
// Static schedule: it=0..6; Z=96(it0)/128; tks_max=63/96/64(last);
// max_z=128 (64 last); mult=1.5 (1.0 last). pmask is always a prefix mask.
//
// Gather layout: 8 threads per k-row (chunks c and c+8 of 16 float4 chunks)
// -> every LDG.128 wavefront delivers a full 128B line. q chunks live in
// registers (loop-invariant). All warp collectives use block-uniform trip
// counts (V is shared state); per-lane work is predicated, never the bound.

#define NEGV  (-32000.0f)
#define FMINV (-1e30f)

__global__ __launch_bounds__(128, 8)
void tree_attn_kernel(const float* __restrict__ q,
                      const float* __restrict__ k,
                      const float* __restrict__ v,
                      float* __restrict__ out)
{
    const int row  = blockIdx.x;          // n*512 + a
    const int n    = row >> 9;
    const int a    = row & 511;
    const int t    = threadIdx.x;         // 0..127
    const int lane = t & 31;
    const int wid  = t >> 5;
    const int c8   = t & 7;               // chunk within row (8 threads/row)
    const int or8  = t >> 3;              // row slot (0..15 per pass)

    __shared__ __align__(16) float qs[64];
    __shared__ __align__(16) float sc[128];
    __shared__ __align__(16) float pr[64];
    __shared__ int      pix[128];
    __shared__ int      np[128];
    __shared__ unsigned bm[128];          // 4096-bit value bitmap
    __shared__ int      wsum[4];

    const float  tsrc = (float)(3585 + a);        // T_SRC - T_DST + 1 + a
    const float* kb   = k + (size_t)n * (4096 * 64);
    const float* vb   = v + (size_t)n * (4096 * 64);

    if (t < 64) qs[t] = q[(size_t)row * 64 + t];
    pix[t] = (t < 96) ? t : 0;
    __syncthreads();

    // q chunks for this thread's row-slot role, held in registers
    const float4 qa = ((const float4*)qs)[c8];
    const float4 qb = ((const float4*)qs)[c8 + 8];

    float ws = 64.0f;
    int   V  = 64;                        // valid (pmask) prefix length

    #pragma unroll 1
    for (int it = 0; it < 7; ++it) {
        const bool  last    = (it == 6);
        const float mult    = last ? 1.0f : 1.5f;
        const int   tks_max = (it == 0) ? 63 : (last ? 64 : 96);
        const int   max_z   = last ? 64 : 128;
        const int   Zcur    = (it == 0) ? 96 : 128;

        // ---- phase A: scores, 8 threads/row, full-line wavefronts ----
        const float ratio = __fdiv_rn(tsrc, ws);
        if (t >= V) sc[t] = NEGV;         // masked tail
        {
            const int npass = (V + 15) >> 4;   // block-uniform
            #pragma unroll 1
            for (int pass = 0; pass < npass; ++pass) {
                const int  r     = pass * 16 + or8;
                const bool valid = (r < V);
                float acc = 0.0f;
                if (valid) {
                    const int x = min((int)rintf(__fmul_rn((float)pix[r], ratio)), 4095);
                    const float4* kr = (const float4*)(kb + (size_t)x * 64);
                    const float4 k0 = __ldg(kr + c8);
                    const float4 k1 = __ldg(kr + c8 + 8);
                    acc  = k0.x*qa.x + k0.y*qa.y + k0.z*qa.z + k0.w*qa.w;
                    acc += k1.x*qb.x + k1.y*qb.y + k1.z*qb.z + k1.w*qb.w;
                }
                acc += __shfl_xor_sync(0xFFFFFFFFu, acc, 1);
                acc += __shfl_xor_sync(0xFFFFFFFFu, acc, 2);
                acc += __shfl_xor_sync(0xFFFFFFFFu, acc, 4);
                if (valid && c8 == 0) sc[r] = acc;
            }
        }
        np[t] = 0;           // NEG-tail rank t -> pixel 0 (pad); overwritten below
        bm[t] = 0u;
        __syncthreads();

        // ---- descending rank over V valid, pairwise-distinct scores ----
        if (t < V) {
            const float  sv  = sc[t];
            const int    nj4 = (V + 3) >> 2;  // sc tail is NEGV (< sv), safe
            const float4* s4 = (const float4*)sc;
            int rank = 0;
            #pragma unroll 4
            for (int j4 = 0; j4 < nj4; ++j4) {
                const float4 o = s4[j4];
                rank += (int)(o.x > sv);
                rank += (int)(o.y > sv);
                rank += (int)(o.z > sv);
                rank += (int)(o.w > sv);
            }
            if (rank < tks_max) np[rank] = pix[t];
        }
        __syncthreads();

        // ---- tks = clip(round(ws/tsrc*64*mult), 1, min(ws-1, Z-1)) ----
        float tkf = rintf(__fmul_rn(__fmul_rn(__fdiv_rn(ws, tsrc), 64.0f), mult));
        tkf = fminf(fmaxf(tkf, 1.0f), fminf(ws - 1.0f, (float)(Zcur - 1)));
        const int tks_eff = min((int)tkf, tks_max);

        // ---- scale-up children into bitmap ----
        const float wsn   = fminf(tsrc, __fmul_rn(ws, 2.0f));
        const float scale = __fdiv_rn(wsn, ws);
        if (t < tks_max) {
            const int p  = np[t];
            const int p0 = min((int)rintf(__fmul_rn((float)p, scale)), 4095);
            atomicOr(&bm[p0 >> 5], 1u << (p0 & 31));
            if (t < tks_eff) {
                const int p1 = (int)rintf(__fmul_rn((float)(p + 1), scale));
                if (p1 - p0 >= 2) {
                    const int pv = min(p0 + 1, 4095);
                    atomicOr(&bm[pv >> 5], 1u << (pv & 31));
                }
            }
        }
        if (t == 127) atomicOr(&bm[0], 1u);   // pad zeros (tks_max < Z always)
        __syncthreads();

        // ---- parallel scan + sorted-unique extraction ----
        unsigned mw = bm[t];
        const int c = __popc(mw);
        int inc = c;
        #pragma unroll
        for (int d = 1; d < 32; d <<= 1) {
            const int o = __shfl_up_sync(0xFFFFFFFFu, inc, d);
            if (lane >= d) inc += o;
        }
        if (lane == 31) wsum[wid] = inc;
        __syncthreads();
        int base = 0, total = 0;
        #pragma unroll
        for (int w2 = 0; w2 < 4; ++w2) {
            const int s = wsum[w2];
            if (w2 < wid) base += s;
            total += s;
        }
        int off = base + inc - c;             // exclusive prefix
        while (mw != 0u && off < max_z) {
            const int b = __ffs(mw) - 1;
            pix[off] = (t << 5) + b;
            mw &= (mw - 1u);
            ++off;
        }
        const int Vn = min(total, max_z);
        if (t >= Vn) pix[t] = 0;              // where(ps<0, 0, ps)
        __syncthreads();

        V  = Vn;
        ws = wsn;
    }

    // ---- final scores over 64 slots (8 threads/row) ----
    {
        if (t >= V && t < 64) sc[t] = FMINV;
        const int npass = (V + 15) >> 4;
        #pragma unroll 1
        for (int pass = 0; pass < npass; ++pass) {
            const int  r     = pass * 16 + or8;
            const bool valid = (r < V);
            float acc = 0.0f;
            if (valid) {
                const int x = min(pix[r], 4095);
                const float4* kr = (const float4*)(kb + (size_t)x * 64);
                const float4 k0 = __ldg(kr + c8);
                const float4 k1 = __ldg(kr + c8 + 8);
                acc  = k0.x*qa.x + k0.y*qa.y + k0.z*qa.z + k0.w*qa.w;
                acc += k1.x*qb.x + k1.y*qb.y + k1.z*qb.z + k1.w*qb.w;
            }
            acc += __shfl_xor_sync(0xFFFFFFFFu, acc, 1);
            acc += __shfl_xor_sync(0xFFFFFFFFu, acc, 2);
            acc += __shfl_xor_sync(0xFFFFFFFFu, acc, 4);
            if (valid && c8 == 0) sc[r] = acc;
        }
    }
    __syncthreads();

    // ---- softmax numerators ----
    if (t < 64) {
        float mx = FMINV;
        const float4* s4 = (const float4*)sc;
        #pragma unroll
        for (int i = 0; i < 16; ++i) {
            const float4 vv = s4[i];
            mx = fmaxf(mx, fmaxf(fmaxf(vv.x, vv.y), fmaxf(vv.z, vv.w)));
        }
        pr[t] = __expf(sc[t] - mx);
    }
    __syncthreads();

    float denom = 0.0f;
    {
        const float4* p4 = (const float4*)pr;
        #pragma unroll
        for (int i = 0; i < 16; ++i) {
            const float4 vv = p4[i];
            denom += vv.x + vv.y + vv.z + vv.w;
        }
    }

    // ---- weighted V gather: 128 threads = 64 cols x 2 z-halves ----
    const int col = t & 63;
    const int zh  = t >> 6;
    float acc = 0.0f;
    #pragma unroll 4
    for (int z = zh * 32; z < zh * 32 + 32; ++z) {
        acc += pr[z] * __ldg(&vb[(size_t)pix[z] * 64 + col]);
    }
    __syncthreads();
    sc[t] = acc;
    __syncthreads();
    if (t < 64)
        out[(size_t)row * 64 + t] = (sc[t] + sc[t + 64]) / denom;
}

extern "C" void kernel_launch(void* const* d_in, const int* in_sizes, int n_in,
                              void* d_out, int out_size)
{
    const float* q = (const float*)d_in[0];   // (8, 512, 64)
    const float* k = (const float*)d_in[1];   // (8, 4096, 64)
    const float* v = (const float*)d_in[2];   // (8, 4096, 64)
    float* out = (float*)d_out;               // (8, 512, 64)
    (void)in_sizes; (void)n_in; (void)out_size;

    tree_attn_kernel<<<8 * 512, 128>>>(q, k, v, out);
}

// round 6
// speedup vs baseline: 2.7215x; 1.0499x over previous
#include <cuda_runtime.h>
#include <cstdint>

// TreeAttention: N=8, T_DST=512, T_SRC=4096, HID=64, K=64, W0=64,
// SCALE_UP=2, OVERSAMPLE=1.5. One CTA (128 threads) per (n, a) row.
// Static schedule: it=0..6; tks_max=63/96.../64(last); max_z=128 (64 last);
// mult=1.5 (1.0 last). pmask is always a prefix mask (length V, shared).
//
// Structure per iteration (4 barriers):
//  A: scores via 8-thread/row gather, 2 rows per loop step (MLP=4), using
//     precomputed indices xs[]            -> sync
//  B: rank (count of greater scores) + owner-thread child expansion into
//     4096-bit bitmap (order-free: bitmap sorts/dedups)      -> sync
//  C: popc + warp scan, wsum                                 -> sync
//  D: extract sorted-unique values -> pix[], precompute next xs[],
//     zero tail, clear bm                                    -> sync
// Exactness: rintf (round-half-even), __fdiv_rn/__fmul_rn (no fast-math
// rewrites); ratio >= 1 => valid scores pairwise distinct => tie-free rank;
// NEG-tail ranks to itself, covered by the unconditional bit-0 pad.

#define NEGV  (-32000.0f)
#define FMINV (-1e30f)

__global__ __launch_bounds__(128, 8)
void tree_attn_kernel(const float* __restrict__ q,
                      const float* __restrict__ k,
                      const float* __restrict__ v,
                      float* __restrict__ out)
{
    const int row  = blockIdx.x;          // n*512 + a
    const int n    = row >> 9;
    const int a    = row & 511;
    const int t    = threadIdx.x;         // 0..127
    const int lane = t & 31;
    const int wid  = t >> 5;
    const int c8   = t & 7;               // chunk within row (8 threads/row)
    const int or8  = t >> 3;              // row slot (0..15)

    __shared__ __align__(16) float qs[64];
    __shared__ __align__(16) float sc[128];
    __shared__ __align__(16) float pr[64];
    __shared__ int      pix[128];
    __shared__ int      xs[128];          // precomputed gather indices
    __shared__ unsigned bm[128];          // 4096-bit value bitmap
    __shared__ int      wsum[4];

    const float  tsrc = (float)(3585 + a);        // T_SRC - T_DST + 1 + a
    const float* kb   = k + (size_t)n * (4096 * 64);
    const float* vb   = v + (size_t)n * (4096 * 64);

    if (t < 64) qs[t] = q[(size_t)row * 64 + t];
    {
        const float r0 = __fdiv_rn(tsrc, 64.0f);
        const int   p  = (t < 96) ? t : 0;
        pix[t] = p;
        xs[t]  = min((int)rintf(__fmul_rn((float)p, r0)), 4095);
    }
    bm[t] = 0u;
    __syncthreads();

    const float4 qa = ((const float4*)qs)[c8];
    const float4 qb = ((const float4*)qs)[c8 + 8];

    float ws = 64.0f;
    int   V  = 64;                        // valid prefix length (shared-state)

    #pragma unroll 1
    for (int it = 0; it < 7; ++it) {
        const bool  last    = (it == 6);
        const float mult    = last ? 1.0f : 1.5f;
        const int   tks_max = (it == 0) ? 63 : (last ? 64 : 96);
        const int   max_z   = last ? 64 : 128;
        const int   Zcur    = (it == 0) ? 96 : 128;

        // ---- A: scores, 8 threads/row, 2 rows in flight ----
        if (t >= V) sc[t] = NEGV;
        #pragma unroll 1
        for (int base = 0; base < V; base += 32) {
            const int  r0 = base + or8;
            const int  r1 = base + 16 + or8;
            const bool v0 = (r0 < V);
            const bool v1 = (r1 < V);
            float acc0 = 0.0f, acc1 = 0.0f;
            if (v0) {
                const float4* kr = (const float4*)(kb + (size_t)xs[r0] * 64);
                const float4 A = __ldg(kr + c8);
                const float4 B = __ldg(kr + c8 + 8);
                acc0  = A.x*qa.x + A.y*qa.y + A.z*qa.z + A.w*qa.w;
                acc0 += B.x*qb.x + B.y*qb.y + B.z*qb.z + B.w*qb.w;
            }
            if (v1) {
                const float4* kr = (const float4*)(kb + (size_t)xs[r1] * 64);
                const float4 A = __ldg(kr + c8);
                const float4 B = __ldg(kr + c8 + 8);
                acc1  = A.x*qa.x + A.y*qa.y + A.z*qa.z + A.w*qa.w;
                acc1 += B.x*qb.x + B.y*qb.y + B.z*qb.z + B.w*qb.w;
            }
            acc0 += __shfl_xor_sync(0xFFFFFFFFu, acc0, 1);
            acc1 += __shfl_xor_sync(0xFFFFFFFFu, acc1, 1);
            acc0 += __shfl_xor_sync(0xFFFFFFFFu, acc0, 2);
            acc1 += __shfl_xor_sync(0xFFFFFFFFu, acc1, 2);
            acc0 += __shfl_xor_sync(0xFFFFFFFFu, acc0, 4);
            acc1 += __shfl_xor_sync(0xFFFFFFFFu, acc1, 4);
            if (v0 && c8 == 0) sc[r0] = acc0;
            if (v1 && c8 == 0) sc[r1] = acc1;
        }
        __syncthreads();

        // ---- tks = clip(round(ws/tsrc*64*mult), 1, min(ws-1, Z-1)) ----
        float tkf = rintf(__fmul_rn(__fmul_rn(__fdiv_rn(ws, tsrc), 64.0f), mult));
        tkf = fminf(fmaxf(tkf, 1.0f), fminf(ws - 1.0f, (float)(Zcur - 1)));
        const int tks_eff = min((int)tkf, tks_max);

        const float wsn   = fminf(tsrc, __fmul_rn(ws, 2.0f));
        const float scale = __fdiv_rn(wsn, ws);

        // ---- B: rank + owner-thread expansion into bitmap ----
        if (t < V) {
            const float  sv  = sc[t];
            const int    nj4 = (V + 3) >> 2;  // sc tail is NEGV (< sv), safe
            const float4* s4 = (const float4*)sc;
            int rank = 0;
            #pragma unroll 4
            for (int j4 = 0; j4 < nj4; ++j4) {
                const float4 o = s4[j4];
                rank += (int)(o.x > sv);
                rank += (int)(o.y > sv);
                rank += (int)(o.z > sv);
                rank += (int)(o.w > sv);
            }
            if (rank < tks_max) {
                const int p  = pix[t];
                const int p0 = min((int)rintf(__fmul_rn((float)p, scale)), 4095);
                atomicOr(&bm[p0 >> 5], 1u << (p0 & 31));
                if (rank < tks_eff) {
                    const int p1 = (int)rintf(__fmul_rn((float)(p + 1), scale));
                    if (p1 - p0 >= 2) {
                        const int pv = min(p0 + 1, 4095);
                        atomicOr(&bm[pv >> 5], 1u << (pv & 31));
                    }
                }
            }
        }
        if (t == 127) atomicOr(&bm[0], 1u);   // pad zeros (tks_max < Z always)
        __syncthreads();

        // ---- C: popc + warp scan ----
        unsigned mw = bm[t];
        const int c = __popc(mw);
        int inc = c;
        #pragma unroll
        for (int d = 1; d < 32; d <<= 1) {
            const int o = __shfl_up_sync(0xFFFFFFFFu, inc, d);
            if (lane >= d) inc += o;
        }
        if (lane == 31) wsum[wid] = inc;
        __syncthreads();

        // ---- D: extract sorted-unique -> pix, next xs; clear bm ----
        int base2 = 0, total = 0;
        #pragma unroll
        for (int w2 = 0; w2 < 4; ++w2) {
            const int s = wsum[w2];
            if (w2 < wid) base2 += s;
            total += s;
        }
        const float ratio_n = __fdiv_rn(tsrc, wsn);   // next-iter gather ratio
        int off = base2 + inc - c;                    // exclusive prefix
        while (mw != 0u && off < max_z) {
            const int b   = __ffs(mw) - 1;
            const int val = (t << 5) + b;
            pix[off] = val;
            xs[off]  = min((int)rintf(__fmul_rn((float)val, ratio_n)), 4095);
            mw &= (mw - 1u);
            ++off;
        }
        const int Vn = min(total, max_z);
        if (t >= Vn) { pix[t] = 0; xs[t] = 0; }       // where(ps<0, 0, ps)
        bm[t] = 0u;
        __syncthreads();

        V  = Vn;
        ws = wsn;
    }

    // ---- final scores over 64 slots (xs == pix here, ratio_n was 1) ----
    {
        if (t >= V && t < 64) sc[t] = FMINV;
        #pragma unroll 1
        for (int base = 0; base < V; base += 32) {
            const int  r0 = base + or8;
            const int  r1 = base + 16 + or8;
            const bool v0 = (r0 < V);
            const bool v1 = (r1 < V);
            float acc0 = 0.0f, acc1 = 0.0f;
            if (v0) {
                const float4* kr = (const float4*)(kb + (size_t)xs[r0] * 64);
                const float4 A = __ldg(kr + c8);
                const float4 B = __ldg(kr + c8 + 8);
                acc0  = A.x*qa.x + A.y*qa.y + A.z*qa.z + A.w*qa.w;
                acc0 += B.x*qb.x + B.y*qb.y + B.z*qb.z + B.w*qb.w;
            }
            if (v1) {
                const float4* kr = (const float4*)(kb + (size_t)xs[r1] * 64);
                const float4 A = __ldg(kr + c8);
                const float4 B = __ldg(kr + c8 + 8);
                acc1  = A.x*qa.x + A.y*qa.y + A.z*qa.z + A.w*qa.w;
                acc1 += B.x*qb.x + B.y*qb.y + B.z*qb.z + B.w*qb.w;
            }
            acc0 += __shfl_xor_sync(0xFFFFFFFFu, acc0, 1);
            acc1 += __shfl_xor_sync(0xFFFFFFFFu, acc1, 1);
            acc0 += __shfl_xor_sync(0xFFFFFFFFu, acc0, 2);
            acc1 += __shfl_xor_sync(0xFFFFFFFFu, acc1, 2);
            acc0 += __shfl_xor_sync(0xFFFFFFFFu, acc0, 4);
            acc1 += __shfl_xor_sync(0xFFFFFFFFu, acc1, 4);
            if (v0 && c8 == 0) sc[r0] = acc0;
            if (v1 && c8 == 0) sc[r1] = acc1;
        }
    }
    __syncthreads();

    // ---- softmax numerators ----
    if (t < 64) {
        float mx = FMINV;
        const float4* s4 = (const float4*)sc;
        #pragma unroll
        for (int i = 0; i < 16; ++i) {
            const float4 vv = s4[i];
            mx = fmaxf(mx, fmaxf(fmaxf(vv.x, vv.y), fmaxf(vv.z, vv.w)));
        }
        pr[t] = __expf(sc[t] - mx);
    }
    __syncthreads();

    float denom = 0.0f;
    {
        const float4* p4 = (const float4*)pr;
        #pragma unroll
        for (int i = 0; i < 16; ++i) {
            const float4 vv = p4[i];
            denom += vv.x + vv.y + vv.z + vv.w;
        }
    }

    // ---- weighted V gather: 128 threads = 64 cols x 2 z-halves ----
    const int col = t & 63;
    const int zh  = t >> 6;
    float acc = 0.0f;
    #pragma unroll 4
    for (int z = zh * 32; z < zh * 32 + 32; ++z) {
        acc += pr[z] * __ldg(&vb[(size_t)pix[z] * 64 + col]);
    }
    __syncthreads();
    sc[t] = acc;
    __syncthreads();
    if (t < 64)
        out[(size_t)row * 64 + t] = (sc[t] + sc[t + 64]) / denom;
}

extern "C" void kernel_launch(void* const* d_in, const int* in_sizes, int n_in,
                              void* d_out, int out_size)
{
    const float* q = (const float*)d_in[0];   // (8, 512, 64)
    const float* k = (const float*)d_in[1];   // (8, 4096, 64)
    const float* v = (const float*)d_in[2];   // (8, 4096, 64)
    float* out = (float*)d_out;               // (8, 512, 64)
    (void)in_sizes; (void)n_in; (void)out_size;

    tree_attn_kernel<<<8 * 512, 128>>>(q, k, v, out);
}

// round 7
// speedup vs baseline: 2.9454x; 1.0823x over previous
#include <cuda_runtime.h>
#include <cstdint>

// TreeAttention: N=8, T_DST=512, T_SRC=4096, HID=64, K=64, W0=64,
// SCALE_UP=2, OVERSAMPLE=1.5. One CTA (128 threads) per (n, a) row.
//
// Iterations 0..5: gather scores (8 threads/row, 2 rows in flight, indices
// precomputed in xs[]), tie-free rank, owner-thread child expansion into a
// 4096-bit bitmap, scan + sorted-unique extraction.
//
// Iteration 6 (specialized): entering it6, ws == tsrc, so ratio == 1
// (xs == pix), scale == 1 (identity expansion, no second child), tks == 64.
// The final mask is (top-64-by-score ∪ {pixel 0}) truncated to the 64
// smallest pixel values; slots are pixel-ascending, so this is a ballot +
// prefix-popc compaction of (pixel, score) pairs held in registers. The
// separate final K-gather and the it6 bitmap machinery are eliminated.
//
// Exactness: rintf (round-half-even), __fdiv_rn/__fmul_rn (no fast-math
// rewrites); ratio >= 1 => valid scores pairwise distinct => tie-free rank;
// NEG tail ranks to itself; pad pixel-0 bit set unconditionally.

#define NEGV  (-32000.0f)
#define FMINV (-1e30f)

__global__ __launch_bounds__(128, 8)
void tree_attn_kernel(const float* __restrict__ q,
                      const float* __restrict__ k,
                      const float* __restrict__ v,
                      float* __restrict__ out)
{
    const int row  = blockIdx.x;          // n*512 + a
    const int n    = row >> 9;
    const int a    = row & 511;
    const int t    = threadIdx.x;         // 0..127
    const int lane = t & 31;
    const int wid  = t >> 5;
    const int c8   = t & 7;               // chunk within row (8 threads/row)
    const int or8  = t >> 3;              // row slot (0..15)

    __shared__ __align__(16) float qs[64];
    __shared__ __align__(16) float sc[128];
    __shared__ __align__(16) float pr[64];
    __shared__ int      pix[128];
    __shared__ int      xs[128];          // precomputed gather indices
    __shared__ unsigned bm[128];          // 4096-bit value bitmap
    __shared__ int      wsum[4];

    const float  tsrc = (float)(3585 + a);        // T_SRC - T_DST + 1 + a
    const float* kb   = k + (size_t)n * (4096 * 64);
    const float* vb   = v + (size_t)n * (4096 * 64);

    if (t < 64) qs[t] = q[(size_t)row * 64 + t];
    {
        const float r0 = __fdiv_rn(tsrc, 64.0f);
        const int   p  = (t < 96) ? t : 0;
        pix[t] = p;
        xs[t]  = min((int)rintf(__fmul_rn((float)p, r0)), 4095);
    }
    bm[t] = 0u;
    __syncthreads();

    const float4 qa = ((const float4*)qs)[c8];
    const float4 qb = ((const float4*)qs)[c8 + 8];

    float ws = 64.0f;
    int   V  = 64;                        // valid prefix length (shared-state)

    #pragma unroll 1
    for (int it = 0; it < 6; ++it) {
        const int tks_max = (it == 0) ? 63 : 96;
        const int Zcur    = (it == 0) ? 96 : 128;

        // ---- A: scores, 8 threads/row, 2 rows in flight ----
        if (t >= V) sc[t] = NEGV;
        #pragma unroll 1
        for (int base = 0; base < V; base += 32) {
            const int  r0 = base + or8;
            const int  r1 = base + 16 + or8;
            const bool v0 = (r0 < V);
            const bool v1 = (r1 < V);
            float acc0 = 0.0f, acc1 = 0.0f;
            if (v0) {
                const float4* kr = (const float4*)(kb + (size_t)xs[r0] * 64);
                const float4 A = __ldg(kr + c8);
                const float4 B = __ldg(kr + c8 + 8);
                acc0  = A.x*qa.x + A.y*qa.y + A.z*qa.z + A.w*qa.w;
                acc0 += B.x*qb.x + B.y*qb.y + B.z*qb.z + B.w*qb.w;
            }
            if (v1) {
                const float4* kr = (const float4*)(kb + (size_t)xs[r1] * 64);
                const float4 A = __ldg(kr + c8);
                const float4 B = __ldg(kr + c8 + 8);
                acc1  = A.x*qa.x + A.y*qa.y + A.z*qa.z + A.w*qa.w;
                acc1 += B.x*qb.x + B.y*qb.y + B.z*qb.z + B.w*qb.w;
            }
            acc0 += __shfl_xor_sync(0xFFFFFFFFu, acc0, 1);
            acc1 += __shfl_xor_sync(0xFFFFFFFFu, acc1, 1);
            acc0 += __shfl_xor_sync(0xFFFFFFFFu, acc0, 2);
            acc1 += __shfl_xor_sync(0xFFFFFFFFu, acc1, 2);
            acc0 += __shfl_xor_sync(0xFFFFFFFFu, acc0, 4);
            acc1 += __shfl_xor_sync(0xFFFFFFFFu, acc1, 4);
            if (v0 && c8 == 0) sc[r0] = acc0;
            if (v1 && c8 == 0) sc[r1] = acc1;
        }
        __syncthreads();

        // ---- tks = clip(round(ws/tsrc*64*1.5), 1, min(ws-1, Z-1)) ----
        float tkf = rintf(__fmul_rn(__fmul_rn(__fdiv_rn(ws, tsrc), 64.0f), 1.5f));
        tkf = fminf(fmaxf(tkf, 1.0f), fminf(ws - 1.0f, (float)(Zcur - 1)));
        const int tks_eff = min((int)tkf, tks_max);

        const float wsn   = fminf(tsrc, __fmul_rn(ws, 2.0f));
        const float scale = __fdiv_rn(wsn, ws);

        // ---- B: rank + owner-thread expansion into bitmap ----
        if (t < V) {
            const float  sv  = sc[t];
            const int    nj4 = (V + 3) >> 2;  // sc tail is NEGV (< sv), safe
            const float4* s4 = (const float4*)sc;
            int rank = 0;
            #pragma unroll 4
            for (int j4 = 0; j4 < nj4; ++j4) {
                const float4 o = s4[j4];
                rank += (int)(o.x > sv);
                rank += (int)(o.y > sv);
                rank += (int)(o.z > sv);
                rank += (int)(o.w > sv);
            }
            if (rank < tks_max) {
                const int p  = pix[t];
                const int p0 = min((int)rintf(__fmul_rn((float)p, scale)), 4095);
                atomicOr(&bm[p0 >> 5], 1u << (p0 & 31));
                if (rank < tks_eff) {
                    const int p1 = (int)rintf(__fmul_rn((float)(p + 1), scale));
                    if (p1 - p0 >= 2) {
                        const int pv = min(p0 + 1, 4095);
                        atomicOr(&bm[pv >> 5], 1u << (pv & 31));
                    }
                }
            }
        }
        if (t == 127) atomicOr(&bm[0], 1u);   // pad zeros (tks_max < Z always)
        __syncthreads();

        // ---- C: popc + warp scan ----
        unsigned mw = bm[t];
        const int c = __popc(mw);
        int inc = c;
        #pragma unroll
        for (int d = 1; d < 32; d <<= 1) {
            const int o = __shfl_up_sync(0xFFFFFFFFu, inc, d);
            if (lane >= d) inc += o;
        }
        if (lane == 31) wsum[wid] = inc;
        __syncthreads();

        // ---- D: extract sorted-unique -> pix, next xs; clear bm ----
        int base2 = 0, total = 0;
        #pragma unroll
        for (int w2 = 0; w2 < 4; ++w2) {
            const int s = wsum[w2];
            if (w2 < wid) base2 += s;
            total += s;
        }
        const float ratio_n = __fdiv_rn(tsrc, wsn);   // next-iter gather ratio
        int off = base2 + inc - c;                    // exclusive prefix
        while (mw != 0u && off < 128) {
            const int b   = __ffs(mw) - 1;
            const int val = (t << 5) + b;
            pix[off] = val;
            xs[off]  = min((int)rintf(__fmul_rn((float)val, ratio_n)), 4095);
            mw &= (mw - 1u);
            ++off;
        }
        const int Vn = min(total, 128);
        if (t >= Vn) { pix[t] = 0; xs[t] = 0; }       // where(ps<0, 0, ps)
        bm[t] = 0u;
        __syncthreads();

        V  = Vn;
        ws = wsn;
    }

    // ==== it6 (ws == tsrc: ratio=1, scale=1, tks=64): direct top-64 ====
    {
        // scores at xs == pix
        if (t >= V) sc[t] = NEGV;
        #pragma unroll 1
        for (int base = 0; base < V; base += 32) {
            const int  r0 = base + or8;
            const int  r1 = base + 16 + or8;
            const bool v0 = (r0 < V);
            const bool v1 = (r1 < V);
            float acc0 = 0.0f, acc1 = 0.0f;
            if (v0) {
                const float4* kr = (const float4*)(kb + (size_t)xs[r0] * 64);
                const float4 A = __ldg(kr + c8);
                const float4 B = __ldg(kr + c8 + 8);
                acc0  = A.x*qa.x + A.y*qa.y + A.z*qa.z + A.w*qa.w;
                acc0 += B.x*qb.x + B.y*qb.y + B.z*qb.z + B.w*qb.w;
            }
            if (v1) {
                const float4* kr = (const float4*)(kb + (size_t)xs[r1] * 64);
                const float4 A = __ldg(kr + c8);
                const float4 B = __ldg(kr + c8 + 8);
                acc1  = A.x*qa.x + A.y*qa.y + A.z*qa.z + A.w*qa.w;
                acc1 += B.x*qb.x + B.y*qb.y + B.z*qb.z + B.w*qb.w;
            }
            acc0 += __shfl_xor_sync(0xFFFFFFFFu, acc0, 1);
            acc1 += __shfl_xor_sync(0xFFFFFFFFu, acc1, 1);
            acc0 += __shfl_xor_sync(0xFFFFFFFFu, acc0, 2);
            acc1 += __shfl_xor_sync(0xFFFFFFFFu, acc1, 2);
            acc0 += __shfl_xor_sync(0xFFFFFFFFu, acc0, 4);
            acc1 += __shfl_xor_sync(0xFFFFFFFFu, acc1, 4);
            if (v0 && c8 == 0) sc[r0] = acc0;
            if (v1 && c8 == 0) sc[r1] = acc1;
        }
        __syncthreads();

        // rank; winner = top-64 score, slot 0 (pixel 0) always included (pad)
        bool win = (t == 0);
        if (t < V) {
            const float  sv  = sc[t];
            const int    nj4 = (V + 3) >> 2;
            const float4* s4 = (const float4*)sc;
            int rank = 0;
            #pragma unroll 4
            for (int j4 = 0; j4 < nj4; ++j4) {
                const float4 o = s4[j4];
                rank += (int)(o.x > sv);
                rank += (int)(o.y > sv);
                rank += (int)(o.z > sv);
                rank += (int)(o.w > sv);
            }
            win = win || (rank < 64);
        }
        const int   myp = pix[t];         // to registers before compaction
        const float mys = sc[t];
        const unsigned wb = __ballot_sync(0xFFFFFFFFu, win);
        if (lane == 0) wsum[wid] = __popc(wb);
        __syncthreads();                  // rank reads of sc done; wsum ready

        int wbase = 0, total = 0;
        #pragma unroll
        for (int w2 = 0; w2 < 4; ++w2) {
            const int s = wsum[w2];
            if (w2 < wid) wbase += s;
            total += s;
        }
        const int cnt = min(total, 64);
        const int pos = wbase + __popc(wb & ((1u << lane) - 1u));
        // slots are pixel-ascending; truncation to 64 smallest pixels ==
        // dropping positions >= 64 (matches bitmap truncation incl. pad case)
        if (win && pos < 64) { pix[pos] = myp; sc[pos] = mys; }
        if (t >= cnt && t < 64) { pix[t] = 0; sc[t] = FMINV; }
        __syncthreads();
    }

    // ---- softmax numerators ----
    if (t < 64) {
        float mx = FMINV;
        const float4* s4 = (const float4*)sc;
        #pragma unroll
        for (int i = 0; i < 16; ++i) {
            const float4 vv = s4[i];
            mx = fmaxf(mx, fmaxf(fmaxf(vv.x, vv.y), fmaxf(vv.z, vv.w)));
        }
        pr[t] = __expf(sc[t] - mx);
    }
    __syncthreads();

    float denom = 0.0f;
    {
        const float4* p4 = (const float4*)pr;
        #pragma unroll
        for (int i = 0; i < 16; ++i) {
            const float4 vv = p4[i];
            denom += vv.x + vv.y + vv.z + vv.w;
        }
    }

    // ---- weighted V gather: 128 threads = 64 cols x 2 z-halves ----
    const int col = t & 63;
    const int zh  = t >> 6;
    float acc = 0.0f;
    #pragma unroll 4
    for (int z = zh * 32; z < zh * 32 + 32; ++z) {
        acc += pr[z] * __ldg(&vb[(size_t)pix[z] * 64 + col]);
    }
    __syncthreads();
    sc[t] = acc;
    __syncthreads();
    if (t < 64)
        out[(size_t)row * 64 + t] = (sc[t] + sc[t + 64]) / denom;
}

extern "C" void kernel_launch(void* const* d_in, const int* in_sizes, int n_in,
                              void* d_out, int out_size)
{
    const float* q = (const float*)d_in[0];   // (8, 512, 64)
    const float* k = (const float*)d_in[1];   // (8, 4096, 64)
    const float* v = (const float*)d_in[2];   // (8, 4096, 64)
    float* out = (float*)d_out;               // (8, 512, 64)
    (void)in_sizes; (void)n_in; (void)out_size;

    tree_attn_kernel<<<8 * 512, 128>>>(q, k, v, out);
}

// round 8
// speedup vs baseline: 3.1103x; 1.0560x over previous
#include <cuda_runtime.h>
#include <cstdint>

// TreeAttention: N=8, T_DST=512, T_SRC=4096, HID=64, K=64, W0=64,
// SCALE_UP=2, OVERSAMPLE=1.5. One CTA (128 threads) per (n, a) row.
//
// Iterations 0..5: gather scores (8 threads/row, 2 rows in flight, indices
// precomputed in xs[]), tie-free rank, owner-thread child expansion into a
// 4096-bit bitmap, scan + sorted-unique extraction.
//
// Iteration 6 (specialized): entering it6, ws == tsrc, so ratio == 1
// (xs == pix), scale == 1 (identity expansion, no second child), tks == 64.
// The final mask is (top-64-by-score ∪ {pixel 0}) truncated to the 64
// smallest pixel values; slots are pixel-ascending, so this is a ballot +
// prefix-popc compaction of (pixel, score) pairs held in registers.
//
// Exactness: rintf (round-half-even), __fdiv_rn/__fmul_rn (no fast-math
// rewrites); ratio >= 1 => valid scores pairwise distinct => tie-free rank;
// NEG tail ranks to itself; pad pixel-0 bit set unconditionally.
//
// Occupancy: launch_bounds(128,10) caps regs at 48 -> 10 CTAs/SM on the
// 64K-reg file (vs 61 regs / 8 CTAs before), lifting issue utilization.

#define NEGV  (-32000.0f)
#define FMINV (-1e30f)

__global__ __launch_bounds__(128, 10)
void tree_attn_kernel(const float* __restrict__ q,
                      const float* __restrict__ k,
                      const float* __restrict__ v,
                      float* __restrict__ out)
{
    const int row  = blockIdx.x;          // n*512 + a
    const int n    = row >> 9;
    const int a    = row & 511;
    const int t    = threadIdx.x;         // 0..127
    const int lane = t & 31;
    const int wid  = t >> 5;
    const int c8   = t & 7;               // chunk within row (8 threads/row)
    const int or8  = t >> 3;              // row slot (0..15)

    __shared__ __align__(16) float qs[64];
    __shared__ __align__(16) float sc[128];
    __shared__ __align__(16) float pr[64];
    __shared__ int      pix[128];
    __shared__ int      xs[128];          // precomputed gather indices
    __shared__ unsigned bm[128];          // 4096-bit value bitmap
    __shared__ int      wsum[4];

    const float  tsrc = (float)(3585 + a);        // T_SRC - T_DST + 1 + a
    const float* kb   = k + (size_t)n * (4096 * 64);

    if (t < 64) qs[t] = q[(size_t)row * 64 + t];
    {
        const float r0 = __fdiv_rn(tsrc, 64.0f);
        const int   p  = (t < 96) ? t : 0;
        pix[t] = p;
        xs[t]  = min((int)rintf(__fmul_rn((float)p, r0)), 4095);
    }
    bm[t] = 0u;
    __syncthreads();

    const float4 qa = ((const float4*)qs)[c8];
    const float4 qb = ((const float4*)qs)[c8 + 8];

    float ws = 64.0f;
    int   V  = 64;                        // valid prefix length (shared-state)

    #pragma unroll 1
    for (int it = 0; it < 6; ++it) {
        const int tks_max = (it == 0) ? 63 : 96;
        const int Zcur    = (it == 0) ? 96 : 128;

        // ---- A: scores, 8 threads/row, 2 rows in flight ----
        if (t >= V) sc[t] = NEGV;
        #pragma unroll 1
        for (int base = 0; base < V; base += 32) {
            const int  r0 = base + or8;
            const int  r1 = base + 16 + or8;
            const bool v0 = (r0 < V);
            const bool v1 = (r1 < V);
            float acc0 = 0.0f, acc1 = 0.0f;
            if (v0) {
                const float4* kr = (const float4*)(kb + (size_t)xs[r0] * 64);
                const float4 A = __ldg(kr + c8);
                const float4 B = __ldg(kr + c8 + 8);
                acc0  = A.x*qa.x + A.y*qa.y + A.z*qa.z + A.w*qa.w;
                acc0 += B.x*qb.x + B.y*qb.y + B.z*qb.z + B.w*qb.w;
            }
            if (v1) {
                const float4* kr = (const float4*)(kb + (size_t)xs[r1] * 64);
                const float4 A = __ldg(kr + c8);
                const float4 B = __ldg(kr + c8 + 8);
                acc1  = A.x*qa.x + A.y*qa.y + A.z*qa.z + A.w*qa.w;
                acc1 += B.x*qb.x + B.y*qb.y + B.z*qb.z + B.w*qb.w;
            }
            acc0 += __shfl_xor_sync(0xFFFFFFFFu, acc0, 1);
            acc1 += __shfl_xor_sync(0xFFFFFFFFu, acc1, 1);
            acc0 += __shfl_xor_sync(0xFFFFFFFFu, acc0, 2);
            acc1 += __shfl_xor_sync(0xFFFFFFFFu, acc1, 2);
            acc0 += __shfl_xor_sync(0xFFFFFFFFu, acc0, 4);
            acc1 += __shfl_xor_sync(0xFFFFFFFFu, acc1, 4);
            if (v0 && c8 == 0) sc[r0] = acc0;
            if (v1 && c8 == 0) sc[r1] = acc1;
        }
        __syncthreads();

        // ---- tks = clip(round(ws/tsrc*64*1.5), 1, min(ws-1, Z-1)) ----
        float tkf = rintf(__fmul_rn(__fmul_rn(__fdiv_rn(ws, tsrc), 64.0f), 1.5f));
        tkf = fminf(fmaxf(tkf, 1.0f), fminf(ws - 1.0f, (float)(Zcur - 1)));
        const int tks_eff = min((int)tkf, tks_max);

        const float wsn   = fminf(tsrc, __fmul_rn(ws, 2.0f));
        const float scale = __fdiv_rn(wsn, ws);

        // ---- B: rank + owner-thread expansion into bitmap ----
        if (t < V) {
            const float  sv  = sc[t];
            const int    nj4 = (V + 3) >> 2;  // sc tail is NEGV (< sv), safe
            const float4* s4 = (const float4*)sc;
            int rank = 0;
            #pragma unroll 4
            for (int j4 = 0; j4 < nj4; ++j4) {
                const float4 o = s4[j4];
                rank += (int)(o.x > sv);
                rank += (int)(o.y > sv);
                rank += (int)(o.z > sv);
                rank += (int)(o.w > sv);
            }
            if (rank < tks_max) {
                const int p  = pix[t];
                const int p0 = min((int)rintf(__fmul_rn((float)p, scale)), 4095);
                atomicOr(&bm[p0 >> 5], 1u << (p0 & 31));
                if (rank < tks_eff) {
                    const int p1 = (int)rintf(__fmul_rn((float)(p + 1), scale));
                    if (p1 - p0 >= 2) {
                        const int pv = min(p0 + 1, 4095);
                        atomicOr(&bm[pv >> 5], 1u << (pv & 31));
                    }
                }
            }
        }
        if (t == 127) atomicOr(&bm[0], 1u);   // pad zeros (tks_max < Z always)
        __syncthreads();

        // ---- C: popc + warp scan ----
        unsigned mw = bm[t];
        const int c = __popc(mw);
        int inc = c;
        #pragma unroll
        for (int d = 1; d < 32; d <<= 1) {
            const int o = __shfl_up_sync(0xFFFFFFFFu, inc, d);
            if (lane >= d) inc += o;
        }
        if (lane == 31) wsum[wid] = inc;
        __syncthreads();

        // ---- D: extract sorted-unique -> pix, next xs; clear bm ----
        int base2 = 0, total = 0;
        #pragma unroll
        for (int w2 = 0; w2 < 4; ++w2) {
            const int s = wsum[w2];
            if (w2 < wid) base2 += s;
            total += s;
        }
        const float ratio_n = __fdiv_rn(tsrc, wsn);   // next-iter gather ratio
        int off = base2 + inc - c;                    // exclusive prefix
        while (mw != 0u && off < 128) {
            const int b   = __ffs(mw) - 1;
            const int val = (t << 5) + b;
            pix[off] = val;
            xs[off]  = min((int)rintf(__fmul_rn((float)val, ratio_n)), 4095);
            mw &= (mw - 1u);
            ++off;
        }
        const int Vn = min(total, 128);
        if (t >= Vn) { pix[t] = 0; xs[t] = 0; }       // where(ps<0, 0, ps)
        bm[t] = 0u;
        __syncthreads();

        V  = Vn;
        ws = wsn;
    }

    // ==== it6 (ws == tsrc: ratio=1, scale=1, tks=64): direct top-64 ====
    {
        // scores at xs == pix
        if (t >= V) sc[t] = NEGV;
        #pragma unroll 1
        for (int base = 0; base < V; base += 32) {
            const int  r0 = base + or8;
            const int  r1 = base + 16 + or8;
            const bool v0 = (r0 < V);
            const bool v1 = (r1 < V);
            float acc0 = 0.0f, acc1 = 0.0f;
            if (v0) {
                const float4* kr = (const float4*)(kb + (size_t)xs[r0] * 64);
                const float4 A = __ldg(kr + c8);
                const float4 B = __ldg(kr + c8 + 8);
                acc0  = A.x*qa.x + A.y*qa.y + A.z*qa.z + A.w*qa.w;
                acc0 += B.x*qb.x + B.y*qb.y + B.z*qb.z + B.w*qb.w;
            }
            if (v1) {
                const float4* kr = (const float4*)(kb + (size_t)xs[r1] * 64);
                const float4 A = __ldg(kr + c8);
                const float4 B = __ldg(kr + c8 + 8);
                acc1  = A.x*qa.x + A.y*qa.y + A.z*qa.z + A.w*qa.w;
                acc1 += B.x*qb.x + B.y*qb.y + B.z*qb.z + B.w*qb.w;
            }
            acc0 += __shfl_xor_sync(0xFFFFFFFFu, acc0, 1);
            acc1 += __shfl_xor_sync(0xFFFFFFFFu, acc1, 1);
            acc0 += __shfl_xor_sync(0xFFFFFFFFu, acc0, 2);
            acc1 += __shfl_xor_sync(0xFFFFFFFFu, acc1, 2);
            acc0 += __shfl_xor_sync(0xFFFFFFFFu, acc0, 4);
            acc1 += __shfl_xor_sync(0xFFFFFFFFu, acc1, 4);
            if (v0 && c8 == 0) sc[r0] = acc0;
            if (v1 && c8 == 0) sc[r1] = acc1;
        }
        __syncthreads();

        // rank; winner = top-64 score, slot 0 (pixel 0) always included (pad)
        bool win = (t == 0);
        if (t < V) {
            const float  sv  = sc[t];
            const int    nj4 = (V + 3) >> 2;
            const float4* s4 = (const float4*)sc;
            int rank = 0;
            #pragma unroll 4
            for (int j4 = 0; j4 < nj4; ++j4) {
                const float4 o = s4[j4];
                rank += (int)(o.x > sv);
                rank += (int)(o.y > sv);
                rank += (int)(o.z > sv);
                rank += (int)(o.w > sv);
            }
            win = win || (rank < 64);
        }
        const int   myp = pix[t];         // to registers before compaction
        const float mys = sc[t];
        const unsigned wb = __ballot_sync(0xFFFFFFFFu, win);
        if (lane == 0) wsum[wid] = __popc(wb);
        __syncthreads();                  // rank reads of sc done; wsum ready

        int wbase = 0, total = 0;
        #pragma unroll
        for (int w2 = 0; w2 < 4; ++w2) {
            const int s = wsum[w2];
            if (w2 < wid) wbase += s;
            total += s;
        }
        const int cnt = min(total, 64);
        const int pos = wbase + __popc(wb & ((1u << lane) - 1u));
        // slots are pixel-ascending; truncation to 64 smallest pixels ==
        // dropping positions >= 64 (matches bitmap truncation incl. pad case)
        if (win && pos < 64) { pix[pos] = myp; sc[pos] = mys; }
        if (t >= cnt && t < 64) { pix[t] = 0; sc[t] = FMINV; }
        __syncthreads();
    }

    // ---- softmax numerators ----
    if (t < 64) {
        float mx = FMINV;
        const float4* s4 = (const float4*)sc;
        #pragma unroll
        for (int i = 0; i < 16; ++i) {
            const float4 vv = s4[i];
            mx = fmaxf(mx, fmaxf(fmaxf(vv.x, vv.y), fmaxf(vv.z, vv.w)));
        }
        pr[t] = __expf(sc[t] - mx);
    }
    __syncthreads();

    float denom = 0.0f;
    {
        const float4* p4 = (const float4*)pr;
        #pragma unroll
        for (int i = 0; i < 16; ++i) {
            const float4 vv = p4[i];
            denom += vv.x + vv.y + vv.z + vv.w;
        }
    }

    // ---- weighted V gather: 128 threads = 64 cols x 2 z-halves ----
    const float* vb  = v + (size_t)n * (4096 * 64);
    const int    col = t & 63;
    const int    zh  = t >> 6;
    float acc = 0.0f;
    #pragma unroll 4
    for (int z = zh * 32; z < zh * 32 + 32; ++z) {
        acc += pr[z] * __ldg(&vb[(size_t)pix[z] * 64 + col]);
    }
    __syncthreads();
    sc[t] = acc;
    __syncthreads();
    if (t < 64)
        out[(size_t)row * 64 + t] = (sc[t] + sc[t + 64]) / denom;
}

extern "C" void kernel_launch(void* const* d_in, const int* in_sizes, int n_in,
                              void* d_out, int out_size)
{
    const float* q = (const float*)d_in[0];   // (8, 512, 64)
    const float* k = (const float*)d_in[1];   // (8, 4096, 64)
    const float* v = (const float*)d_in[2];   // (8, 4096, 64)
    float* out = (float*)d_out;               // (8, 512, 64)
    (void)in_sizes; (void)n_in; (void)out_size;

    tree_attn_kernel<<<8 * 512, 128>>>(q, k, v, out);
}